// round 14
// baseline (speedup 1.0000x reference)
#include <cuda_runtime.h>
#include <cuda_fp16.h>
#include <cstdint>

#define DD    512
#define ROWS  4096
#define NLAB  16
#define KTOT  576            // 512 feat + 16 counts/bias + 48 zero pad
#define BK    64             // halves per stage
#define NSTG  9              // 576/64
#define NBUF  4              // bulk-copy ring depth
#define BLKB_A 16384         // bytes per 128x64 A stage block
#define BLKB_B 8192          // bytes per  64x64 B stage block

// Tiled scratch: g_A = [m_tile(32)][stage(9)][128 rows x 64 halves, swizzled]
//                g_B = [n_tile(8) ][stage(9)][ 64 rows x 64 halves, swizzled]
// Swizzle: within a block, row r / byte kb -> (r*128 + kb) ^ ((r&7)<<4)
__device__ __align__(16) __half g_A[ROWS / 128 * NSTG * (BLKB_A / 2)];   // 4.7 MB
__device__ __align__(16) __half g_B[DD / 64 * NSTG * (BLKB_B / 2)];      // 0.59 MB

__device__ __forceinline__ uint32_t swz(int row, int byteInRow) {
    return (uint32_t)((row * 128 + byteInRow) ^ ((row & 7) << 4));
}

// ---------------------------------------------------------------------------
// prep_kernel: grid 2560 x 128 threads.
//  blocks 0..2047  : A path, 2 feat rows each (feat->half, label counts, pad)
//  blocks 2048..2559: B path, one o-row each (w0+w1, bias^T, pad)
// ---------------------------------------------------------------------------
__global__ __launch_bounds__(128) void prep_kernel(const float* __restrict__ feat,
                                                   const int* __restrict__ g32,
                                                   const float* __restrict__ w,
                                                   const float* __restrict__ bias) {
    const int b = blockIdx.x, t = threadIdx.x;
    char* const gA = (char*)g_A;
    char* const gB = (char*)g_B;
    if (b < 2048) {
        __shared__ int c[2][NLAB];
        __shared__ int anyOdd;
        const int rl = t >> 6;                  // row within block (0/1)
        const int r  = b * 2 + rl;
        const int colg = (t & 63) * 8;          // half col 0..504, mult of 8
        if (t < 2 * NLAB) c[t >> 4][t & 15] = 0;
        if (t == 0) anyOdd = 0;
        __syncthreads();

        // int64-vs-int32 probe (labels<16 => odd int32 slots all zero iff i64)
        if (t < 64 && g32[2048 * t + 1]) atomicOr(&anyOdd, 1);

        const float4* fp = (const float4*)(feat + (size_t)r * DD + colg);
        float4 v0 = fp[0], v1 = fp[1];
        __half2 h0 = __floats2half2_rn(v0.x, v0.y);
        __half2 h1 = __floats2half2_rn(v0.z, v0.w);
        __half2 h2 = __floats2half2_rn(v1.x, v1.y);
        __half2 h3 = __floats2half2_rn(v1.z, v1.w);
        uint4 pk;
        pk.x = *(uint32_t*)&h0; pk.y = *(uint32_t*)&h1;
        pk.z = *(uint32_t*)&h2; pk.w = *(uint32_t*)&h3;
        {
            const int stage = colg >> 6, kin = colg & 63, rr = r & 127;
            size_t base = (size_t)((r >> 7) * NSTG + stage) * BLKB_A;
            *(uint4*)(gA + base + swz(rr, kin * 2)) = pk;
        }
        __syncthreads();

        const int is64 = (anyOdd == 0);
        int l0, l1;
        const int pair = r * 64 + (t & 63);
        if (is64) {
            longlong2 q = ((const longlong2*)g32)[pair];
            l0 = (int)q.x; l1 = (int)q.y;
        } else {
            int2 q = ((const int2*)g32)[pair];
            l0 = q.x; l1 = q.y;
        }
        atomicAdd(&c[rl][l0 & (NLAB - 1)], 1);
        atomicAdd(&c[rl][l1 & (NLAB - 1)], 1);
        __syncthreads();

        // stage-8 block: counts at kin 0..15, zeros kin 16..63
        if (t < 32) {
            int rr2 = t >> 4, l = t & 15;
            int r2 = b * 2 + rr2, rr = r2 & 127;
            size_t base = (size_t)((r2 >> 7) * NSTG + 8) * BLKB_A;
            *(__half*)(gA + base + swz(rr, l * 2)) = __float2half_rn((float)c[rr2][l]);
        } else if (t < 44) {
            int u = t - 32;                     // 0..11
            int rr2 = u / 6, j = u % 6;         // 6 x 16B chunks: bytes 32..127
            int r2 = b * 2 + rr2, rr = r2 & 127;
            size_t base = (size_t)((r2 >> 7) * NSTG + 8) * BLKB_A;
            *(uint4*)(gA + base + swz(rr, 32 + j * 16)) = make_uint4(0, 0, 0, 0);
        }
    } else {
        const int o = b - 2048, oo = o & 63;   // 64-row B blocks
        if (t < 64) {
            const int k = t * 8;
            const float4* p0 = (const float4*)(w + (size_t)o * DD + k);
            const float4* p1 = (const float4*)(w + (size_t)DD * DD + (size_t)o * DD + k);
            float4 a0 = p0[0], a1 = p0[1], b0 = p1[0], b1 = p1[1];
            __half2 h0 = __floats2half2_rn(a0.x + b0.x, a0.y + b0.y);
            __half2 h1 = __floats2half2_rn(a0.z + b0.z, a0.w + b0.w);
            __half2 h2 = __floats2half2_rn(a1.x + b1.x, a1.y + b1.y);
            __half2 h3 = __floats2half2_rn(a1.z + b1.z, a1.w + b1.w);
            uint4 pk;
            pk.x = *(uint32_t*)&h0; pk.y = *(uint32_t*)&h1;
            pk.z = *(uint32_t*)&h2; pk.w = *(uint32_t*)&h3;
            size_t base = (size_t)((o >> 6) * NSTG + (k >> 6)) * BLKB_B;
            *(uint4*)(gB + base + swz(oo, (k & 63) * 2)) = pk;
        } else {
            const int u = t - 64;               // 0..63 -> stage 8, kin u
            float v = (u < NLAB) ? bias[u * DD + o] : 0.f;
            size_t base = (size_t)((o >> 6) * NSTG + 8) * BLKB_B;
            *(__half*)(gB + base + swz(oo, u * 2)) = __float2half_rn(v);
        }
    }
}

// ============================ mma GEMM =====================================
__device__ __forceinline__ uint32_t smem_u32(const void* p) {
    uint32_t a;
    asm("{ .reg .u64 t; cvta.to.shared.u64 t, %1; cvt.u32.u64 %0, t; }" : "=r"(a) : "l"(p));
    return a;
}
#define MBAR_INIT(addr, cnt) \
    asm volatile("mbarrier.init.shared.b64 [%0], %1;" :: "r"(addr), "r"((uint32_t)(cnt)) : "memory")
#define MBAR_EXPECT_TX(addr, bytes) \
    asm volatile("mbarrier.arrive.expect_tx.shared.b64 _, [%0], %1;" :: "r"(addr), "r"((uint32_t)(bytes)) : "memory")
#define MBAR_WAIT(addr, par) do {                                            \
    asm volatile("{\n\t.reg .pred P;\n\tWL_%=:\n\t"                           \
        "mbarrier.try_wait.parity.acquire.cta.shared::cta.b64 P, [%0], %1, 0x989680;\n\t" \
        "@P bra.uni WD_%=;\n\tbra.uni WL_%=;\n\tWD_%=:\n\t}"                  \
        :: "r"(addr), "r"((uint32_t)(par)) : "memory"); } while (0)
#define BULK_G2S(dst, src, bytes, mbar) \
    asm volatile("cp.async.bulk.shared::cluster.global.mbarrier::complete_tx::bytes " \
        "[%0], [%1], %2, [%3];" \
        :: "r"(dst), "l"(src), "r"((uint32_t)(bytes)), "r"(mbar) : "memory")
#define LDM_X4(r0, r1, r2, r3, addr) \
    asm volatile("ldmatrix.sync.aligned.m8n8.x4.shared.b16 {%0,%1,%2,%3}, [%4];" \
        : "=r"(r0), "=r"(r1), "=r"(r2), "=r"(r3) : "r"(addr))
#define MMA16816(c, a, b) \
    asm volatile("mma.sync.aligned.m16n8k16.row.col.f32.f16.f16.f32 " \
        "{%0,%1,%2,%3}, {%4,%5,%6,%7}, {%8,%9}, {%0,%1,%2,%3};" \
        : "+f"((c)[0]), "+f"((c)[1]), "+f"((c)[2]), "+f"((c)[3]) \
        : "r"((a)[0]), "r"((a)[1]), "r"((a)[2]), "r"((a)[3]), "r"((b)[0]), "r"((b)[1]))

// smem: [0:32) mbarriers (4 x 8B), data at 1024: buf i = A 16K + B 8K
#define SM_DATA  1024
#define BUFBYTES (BLKB_A + BLKB_B)              // 24576
#define GEMM_SMEM (SM_DATA + NBUF * BUFBYTES)   // 99328 -> 2 CTAs/SM

// out[m][n] = sum_k A[m][k]*B[n][k] + feat[m][n]
// 128x64 CTA tile, 256 threads = 8 warps (4x2), warp tile 32x32.
// 4-deep bulk ring; 2 CTAs co-resident per SM hide each other's stalls.
__global__ __launch_bounds__(256) void gemm_mma_kernel(const float* __restrict__ feat,
                                                       float* __restrict__ out) {
    extern __shared__ __align__(16) char smem[];
    const uint32_t sb = smem_u32(smem);

    const int tid = threadIdx.x, wid = tid >> 5, lane = tid & 31;
    const int g = lane >> 2, tg = lane & 3;
    const int wm0 = (wid >> 1) * 32;          // warp row origin in tile
    const int wn0 = (wid & 1) * 32;           // warp col origin in tile
    const int mt = blockIdx.y, nt = blockIdx.x;
    const int m0 = mt * 128, n0 = nt * 64;
    const char* const gA = (const char*)g_A;
    const char* const gB = (const char*)g_B;

    if (tid == 0) {
        #pragma unroll
        for (int i = 0; i < NBUF; i++) MBAR_INIT(sb + 8 * i, 1);
    }
    __syncthreads();

    auto load_stage = [&](int s, int buf) {   // tid0 only
        const uint32_t mb = sb + 8 * buf;
        const uint32_t dst = sb + SM_DATA + buf * BUFBYTES;
        MBAR_EXPECT_TX(mb, BUFBYTES);
        BULK_G2S(dst,          gA + (size_t)(mt * NSTG + s) * BLKB_A, BLKB_A, mb);
        BULK_G2S(dst + BLKB_A, gB + (size_t)(nt * NSTG + s) * BLKB_B, BLKB_B, mb);
    };
    if (tid == 0) {
        #pragma unroll
        for (int i = 0; i < NBUF - 1; i++) load_stage(i, i);
    }

    // Prefetch epilogue feat operands (latency amortized over the mainloop)
    float2 fpre[2][4][2];
    #pragma unroll
    for (int mi = 0; mi < 2; mi++) {
        const int row0 = m0 + wm0 + mi * 16 + g;
        #pragma unroll
        for (int nj = 0; nj < 4; nj++) {
            const int col = n0 + wn0 + nj * 8 + tg * 2;
            fpre[mi][nj][0] = *(const float2*)(feat + (size_t)row0 * DD + col);
            fpre[mi][nj][1] = *(const float2*)(feat + (size_t)(row0 + 8) * DD + col);
        }
    }

    float c[2][4][4];
    #pragma unroll
    for (int i = 0; i < 2; i++)
        #pragma unroll
        for (int j = 0; j < 4; j++)
            #pragma unroll
            for (int q = 0; q < 4; q++) c[i][j][q] = 0.f;

    const int lrow = lane & 15;
    const int lcolB = ((lane >> 4) << 3) * 2;     // byte offset {0,16} within k16

    for (int s = 0; s < NSTG; s++) {
        const int buf = s & (NBUF - 1);
        MBAR_WAIT(sb + 8 * buf, (s / NBUF) & 1);
        const uint32_t aT = sb + SM_DATA + buf * BUFBYTES;
        const uint32_t bT = aT + BLKB_A;
        #pragma unroll
        for (int ks = 0; ks < 4; ks++) {      // four k16 steps per stage
            uint32_t a[2][4], b[4][2];
            #pragma unroll
            for (int mi = 0; mi < 2; mi++) {
                const int row = wm0 + mi * 16 + lrow;
                LDM_X4(a[mi][0], a[mi][1], a[mi][2], a[mi][3],
                       aT + swz(row, ks * 32 + lcolB));
            }
            #pragma unroll
            for (int nb = 0; nb < 2; nb++) {
                const int row = wn0 + nb * 16 + lrow;
                uint32_t t0, t1, t2, t3;
                LDM_X4(t0, t1, t2, t3, bT + swz(row, ks * 32 + lcolB));
                b[2 * nb][0] = t0; b[2 * nb + 1][0] = t1;
                b[2 * nb][1] = t2; b[2 * nb + 1][1] = t3;
            }
            #pragma unroll
            for (int mi = 0; mi < 2; mi++)
                #pragma unroll
                for (int nj = 0; nj < 4; nj++)
                    MMA16816(c[mi][nj], a[mi], b[nj]);
        }
        __syncthreads();                      // ring reuse guard (8 warps only)
        if (tid == 0 && s + NBUF - 1 < NSTG)
            load_stage(s + NBUF - 1, (s + NBUF - 1) & (NBUF - 1));
    }

    // ---- epilogue: += prefetched feat, fp32 out
    #pragma unroll
    for (int mi = 0; mi < 2; mi++) {
        const int row0 = m0 + wm0 + mi * 16 + g;
        const int row1 = row0 + 8;
        #pragma unroll
        for (int nj = 0; nj < 4; nj++) {
            const int col = n0 + wn0 + nj * 8 + tg * 2;
            float2 f0 = fpre[mi][nj][0], f1 = fpre[mi][nj][1];
            float2 o0 = make_float2(c[mi][nj][0] + f0.x, c[mi][nj][1] + f0.y);
            float2 o1 = make_float2(c[mi][nj][2] + f1.x, c[mi][nj][3] + f1.y);
            *(float2*)(out + (size_t)row0 * DD + col) = o0;
            *(float2*)(out + (size_t)row1 * DD + col) = o1;
        }
    }
}

// ================================ host =====================================
extern "C" void kernel_launch(void* const* d_in, const int* in_sizes, int n_in,
                              void* d_out, int out_size) {
    const float* feat = (const float*)d_in[0];
    const int*   g32  = (const int*)d_in[1];
    const float* w    = (const float*)d_in[2];
    const float* bias = (const float*)d_in[3];
    float* out = (float*)d_out;

    static bool attr_set = false;
    if (!attr_set) {
        cudaFuncSetAttribute(gemm_mma_kernel,
                             cudaFuncAttributeMaxDynamicSharedMemorySize, GEMM_SMEM);
        attr_set = true;
    }

    prep_kernel<<<2560, 128>>>(feat, g32, w, bias);
    dim3 grid(DD / 64, ROWS / 128);                 // (8, 32) = 256 CTAs
    gemm_mma_kernel<<<grid, 256, GEMM_SMEM>>>(feat, out);
}